// round 5
// baseline (speedup 1.0000x reference)
#include <cuda_runtime.h>
#include <cuda_fp16.h>
#include <cstdint>

#define IN_DIM   4096
#define OUT_DIM  16384
#define MDIM     32

#define NTILE    128            // output cols per CTA
#define KC       64             // K per chunk (64 halves = 128B rows, SW128)
#define NCHUNK   (IN_DIM / KC)  // 64
#define K_PER_MMA 16            // fp16: 32B per MMA step
#define MMA_M    128
#define MMA_IDESC ((1u<<4) | ((NTILE/8)<<17) | ((MMA_M/16)<<24))   // f32 acc, f16 in

// ---- dynamic smem layout (bytes)
#define SM_TMEMPTR 0
#define SM_MBAR0   8
#define SM_MBAR1   16
#define SM_A0      1024
#define SM_A1      (SM_A0 + 16384)
#define SM_B0      (SM_A1 + 16384)
#define SM_B1      (SM_B0 + 16384)
#define SM_EP      (SM_B1 + 16384)          // 32 x 33 floats
#define SM_Y       (SM_EP + 32*33*4)        // 32 x 132 floats
#define SMEM_TOTAL (SM_Y + 32*132*4)

// arch-specific gate: tcgen05 only exists in the sm_103a/sm_100a-specific targets.
// The harness also runs a plain compute_103 ptxas pass which must never see it.
#if defined(__CUDA_ARCH_FEAT_SM103_ALL) || defined(__CUDA_ARCH_FEAT_SM100_ALL) || \
    defined(__CUDA_ARCH_FEAT_SM101_ALL) || \
    (defined(__CUDA_ARCH_SPECIFIC__)) || (defined(__CUDA_ARCH_FAMILY_SPECIFIC__))
#define TC_OK 1
#else
#define TC_OK 0
#endif

// pre-converted A: rows 0..31 = hi(x), rows 32..63 = lo(x), fp16, row-major [64][4096]
__device__ __half g_A[64 * IN_DIM];

#define SW128(o) ((o) ^ (((o) >> 3) & 0x70))

#if TC_OK
__device__ __forceinline__ uint32_t elect1() {
    uint32_t p;
    asm volatile("{\n\t.reg .pred p;\n\telect.sync _|p, 0xFFFFFFFF;\n\tselp.b32 %0, 1, 0, p;\n\t}" : "=r"(p));
    return p;
}

__device__ __forceinline__ void mma_f16_ss(uint32_t d_tmem, uint64_t a_desc,
                                           uint64_t b_desc, uint32_t idesc, uint32_t en) {
    asm volatile(
        "{\n\t.reg .pred p;\n\tsetp.ne.u32 p, %4, 0;\n\t"
        "tcgen05.mma.cta_group::1.kind::f16 [%0], %1, %2, %3, {%5, %5, %5, %5}, p;\n\t}"
        :: "r"(d_tmem), "l"(a_desc), "l"(b_desc), "r"(idesc), "r"(en), "r"(0u)
        : "memory");
}

// K-major SW128 smem descriptor (LBO=1, SBO=64, version=1, layout=SW128)
__device__ __forceinline__ uint64_t mk_desc(uint32_t saddr) {
    return ((uint64_t)2 << 61) | ((uint64_t)1 << 46) | ((uint64_t)64 << 32)
         | ((uint64_t)1 << 16) | ((uint64_t)(saddr >> 4) & 0x3FFF);
}
#endif

__global__ void xsplit_kernel(const float* __restrict__ x) {
    int i = blockIdx.x * blockDim.x + threadIdx.x;   // 0 .. 32*4096-1
    if (i >= MDIM * IN_DIM) return;
    float v  = x[i];
    __half h = __float2half_rn(v);
    __half l = __float2half_rn(v - __half2float(h));
    int m = i / IN_DIM, k = i % IN_DIM;
    g_A[m * IN_DIM + k]        = h;
    g_A[(m + 32) * IN_DIM + k] = l;
}

__global__ __launch_bounds__(256, 1)
void qgemm_tc(const int* __restrict__ wq,
              const int* __restrict__ zerop,
              const float* __restrict__ scalep,
              const float* __restrict__ bias,
              float* __restrict__ out)
{
#if TC_OK
    extern __shared__ char smem[];
    const uint32_t sb = (uint32_t)__cvta_generic_to_shared(smem);
    const int t   = threadIdx.x;
    const int wid = t >> 5;
    const int lid = t & 31;
    const int o0  = blockIdx.x * NTILE;

    // half2 constant: -(1024 + zero) in both lanes
    const int zero = zerop[0];
    const __half  hz  = __int2half_rn(-1024 - zero);
    const __half2 hz2 = __halves2half2(hz, hz);

    // ---- init: TMEM alloc, mbarriers, zero A pad rows (64..127 of both A bufs)
    if (wid == 0) {
        asm volatile("tcgen05.alloc.cta_group::1.sync.aligned.shared::cta.b32 [%0], %1;"
                     :: "r"(sb + SM_TMEMPTR), "r"(128u) : "memory");
    }
    if (t == 0) {
        asm volatile("mbarrier.init.shared.b64 [%0], 1;" :: "r"(sb + SM_MBAR0) : "memory");
        asm volatile("mbarrier.init.shared.b64 [%0], 1;" :: "r"(sb + SM_MBAR1) : "memory");
    }
    // zero pad rows: bytes [64*128, 128*128) of each A buffer = 8KB each
    {
        uint4 z = make_uint4(0, 0, 0, 0);
        for (int i = t; i < 512; i += 256) {           // 512 * 16B = 8KB
            *(uint4*)(smem + SM_A0 + 8192 + i * 16) = z;
            *(uint4*)(smem + SM_A1 + 8192 + i * 16) = z;
        }
    }
    __syncthreads();
    uint32_t tmem;
    asm volatile("ld.shared.b32 %0, [%1];" : "=r"(tmem) : "r"(sb + SM_TMEMPTR));

    // ---- load maps
    // B: thread -> row r = t>>1 (o), half h = t&1 (k range [32h,32h+32)); 8 int4 LDG
    const int br = t >> 1, bh = t & 1;
    const int* bbase = wq + (size_t)(o0 + br) * IN_DIM + bh * 32;
    // A: thread -> row r = t>>2 (0..63), seg = t&3 (32B); 2 int4 LDG
    const int ar = t >> 2, as = t & 3;
    const char* abase = (const char*)g_A + ((size_t)ar * IN_DIM) * 2 + as * 32;

    int4 qreg[2][8];
    int4 areg[2][2];

#define LDGC(set, c)                                                              \
    do {                                                                          \
        _Pragma("unroll")                                                         \
        for (int j = 0; j < 8; j++)                                               \
            qreg[set][j] = *(const int4*)(bbase + (c) * KC + j * 4);              \
        areg[set][0] = *(const int4*)(abase + (c) * (KC * 2));                    \
        areg[set][1] = *(const int4*)(abase + (c) * (KC * 2) + 16);               \
    } while (0)

#define STSC(set, buf)                                                            \
    do {                                                                          \
        const uint32_t bB = sb + ((buf) ? SM_B1 : SM_B0);                         \
        _Pragma("unroll")                                                         \
        for (int g = 0; g < 4; g++) {                                             \
            int4 qa = qreg[set][2 * g], qb = qreg[set][2 * g + 1];                 \
            uint32_t u0 = ((uint32_t)qa.x | ((uint32_t)qa.y << 16)) + 0x64006400u;\
            uint32_t u1 = ((uint32_t)qa.z | ((uint32_t)qa.w << 16)) + 0x64006400u;\
            uint32_t u2 = ((uint32_t)qb.x | ((uint32_t)qb.y << 16)) + 0x64006400u;\
            uint32_t u3 = ((uint32_t)qb.z | ((uint32_t)qb.w << 16)) + 0x64006400u;\
            __half2 h0 = __hadd2(*(__half2*)&u0, hz2);                            \
            __half2 h1 = __hadd2(*(__half2*)&u1, hz2);                            \
            __half2 h2 = __hadd2(*(__half2*)&u2, hz2);                            \
            __half2 h3 = __hadd2(*(__half2*)&u3, hz2);                            \
            uint32_t off = SW128((uint32_t)(br * 128 + bh * 64 + g * 16));        \
            asm volatile("st.shared.v4.b32 [%0], {%1, %2, %3, %4};"               \
                :: "r"(bB + off), "r"(*(uint32_t*)&h0), "r"(*(uint32_t*)&h1),     \
                   "r"(*(uint32_t*)&h2), "r"(*(uint32_t*)&h3) : "memory");        \
        }                                                                         \
        const uint32_t bA = sb + ((buf) ? SM_A1 : SM_A0);                         \
        _Pragma("unroll")                                                         \
        for (int j = 0; j < 2; j++) {                                             \
            uint32_t off = SW128((uint32_t)(ar * 128 + as * 32 + j * 16));        \
            int4 v = areg[set][j];                                                \
            asm volatile("st.shared.v4.b32 [%0], {%1, %2, %3, %4};"               \
                :: "r"(bA + off), "r"(v.x), "r"(v.y), "r"(v.z), "r"(v.w) : "memory"); \
        }                                                                         \
    } while (0)

    int ph[2] = {0, 0};

    LDGC(0, 0);

    for (int c = 0; c < NCHUNK; c++) {
        const int buf = c & 1, set = c & 1;

        if (c >= 2) {
            const uint32_t mb = sb + (buf ? SM_MBAR1 : SM_MBAR0);
            uint32_t done;
            asm volatile(
                "{\n\t.reg .pred p;\n\t"
                "mbarrier.try_wait.parity.acquire.cta.shared::cta.b64 p, [%1], %2;\n\t"
                "selp.b32 %0, 1, 0, p;\n\t}" : "=r"(done) : "r"(mb), "r"(ph[buf]) : "memory");
            if (!done) {
                asm volatile(
                    "{\n\t.reg .pred P1;\n\tW0_%=:\n\t"
                    "mbarrier.try_wait.parity.acquire.cta.shared::cta.b64 P1, [%0], %1, 0x989680;\n\t"
                    "@P1 bra.uni W1_%=;\n\tbra.uni W0_%=;\n\tW1_%=:\n\t}"
                    :: "r"(mb), "r"(ph[buf]) : "memory");
            }
            ph[buf] ^= 1;
        }

        if (c + 1 < NCHUNK) LDGC(set ^ 1, c + 1);

        STSC(set, buf);

        asm volatile("fence.proxy.async.shared::cta;" ::: "memory");
        __syncthreads();

        if (wid == 0 && elect1()) {
            uint64_t ad = mk_desc(sb + (buf ? SM_A1 : SM_A0));
            uint64_t bd = mk_desc(sb + (buf ? SM_B1 : SM_B0));
#pragma unroll
            for (int s = 0; s < KC / K_PER_MMA; s++)
                mma_f16_ss(tmem, ad + s * 2, bd + s * 2, MMA_IDESC,
                           (c > 0 || s > 0) ? 1u : 0u);
            const uint32_t mb = sb + (buf ? SM_MBAR1 : SM_MBAR0);
            asm volatile(
                "tcgen05.commit.cta_group::1.mbarrier::arrive::one.shared::cluster.b64 [%0];"
                :: "r"(mb) : "memory");
        }
    }

    // ---- drain both buffers
#pragma unroll
    for (int b = 0; b < 2; b++) {
        const uint32_t mb = sb + (b ? SM_MBAR1 : SM_MBAR0);
        asm volatile(
            "{\n\t.reg .pred P1;\n\tW2_%=:\n\t"
            "mbarrier.try_wait.parity.acquire.cta.shared::cta.b64 P1, [%0], %1, 0x989680;\n\t"
            "@P1 bra.uni W3_%=;\n\tbra.uni W2_%=;\n\tW3_%=:\n\t}"
            :: "r"(mb), "r"(ph[b]) : "memory");
    }
    asm volatile("tcgen05.fence::after_thread_sync;" ::: "memory");

    // ---- epilogue: warp0 holds hi rows (m=lid), warp1 holds lo rows
    const float scale = scalep[0];
    float* Ep = (float*)(smem + SM_EP);     // [32][33]
    float* Ys = (float*)(smem + SM_Y);      // [32][132]

    for (int s = 0; s < 4; s++) {
        uint32_t d[32];
        if (wid < 2) {
            asm volatile(
                "tcgen05.ld.sync.aligned.32x32b.x32.b32 "
                "{%0,%1,%2,%3,%4,%5,%6,%7,%8,%9,%10,%11,%12,%13,%14,%15,"
                "%16,%17,%18,%19,%20,%21,%22,%23,%24,%25,%26,%27,%28,%29,%30,%31}, [%32];"
                : "=r"(d[0]), "=r"(d[1]), "=r"(d[2]), "=r"(d[3]), "=r"(d[4]), "=r"(d[5]),
                  "=r"(d[6]), "=r"(d[7]), "=r"(d[8]), "=r"(d[9]), "=r"(d[10]), "=r"(d[11]),
                  "=r"(d[12]), "=r"(d[13]), "=r"(d[14]), "=r"(d[15]), "=r"(d[16]), "=r"(d[17]),
                  "=r"(d[18]), "=r"(d[19]), "=r"(d[20]), "=r"(d[21]), "=r"(d[22]), "=r"(d[23]),
                  "=r"(d[24]), "=r"(d[25]), "=r"(d[26]), "=r"(d[27]), "=r"(d[28]), "=r"(d[29]),
                  "=r"(d[30]), "=r"(d[31])
                : "r"(tmem + s * 32));
            asm volatile("tcgen05.wait::ld.sync.aligned;" ::: "memory");
        }
        if (wid == 1) {
#pragma unroll
            for (int cc = 0; cc < 32; cc++) Ep[lid * 33 + cc] = __uint_as_float(d[cc]);
        }
        __syncthreads();
        if (wid == 0) {
#pragma unroll
            for (int cc = 0; cc < 32; cc++) {
                float hi = __uint_as_float(d[cc]);
                float lo = Ep[lid * 33 + cc];
                float b  = bias[o0 + s * 32 + cc];
                Ys[lid * 132 + s * 32 + cc] = fmaf(scale, hi + lo, b);
            }
        }
        __syncthreads();
    }

    // ---- coalesced store: 32 rows x 128 cols
    {
        const int m = t >> 3, q8 = t & 7;
#pragma unroll
        for (int i = 0; i < 4; i++) {
            const int q = q8 + 8 * i;                 // float4 index 0..31
            float4 v = *(const float4*)(Ys + m * 132 + q * 4);
            *(float4*)(out + (size_t)m * OUT_DIM + o0 + q * 4) = v;
        }
    }

    __syncthreads();
    if (t == 0) {
        asm volatile("mbarrier.inval.shared.b64 [%0];" :: "r"(sb + SM_MBAR0) : "memory");
        asm volatile("mbarrier.inval.shared.b64 [%0];" :: "r"(sb + SM_MBAR1) : "memory");
    }
    __syncthreads();
    if (wid == 0) {
        asm volatile("tcgen05.dealloc.cta_group::1.sync.aligned.b32 %0, %1;"
                     :: "r"(tmem), "r"(128u));
    }
#endif  // TC_OK
}

extern "C" void kernel_launch(void* const* d_in, const int* in_sizes, int n_in,
                              void* d_out, int out_size)
{
    const float* x     = (const float*)d_in[0];
    const int*   wq    = (const int*)  d_in[1];
    const int*   zero  = (const int*)  d_in[2];
    const float* scale = (const float*)d_in[3];
    const float* bias  = (const float*)d_in[4];
    float*       out   = (float*)d_out;

    cudaFuncSetAttribute(qgemm_tc, cudaFuncAttributeMaxDynamicSharedMemorySize, SMEM_TOTAL);

    xsplit_kernel<<<(MDIM * IN_DIM + 255) / 256, 256>>>(x);
    qgemm_tc<<<OUT_DIM / NTILE, 256, SMEM_TOTAL>>>(wq, zero, scale, bias, out);
}